// round 16
// baseline (speedup 1.0000x reference)
#include <cuda_runtime.h>
#include <cuda_bf16.h>
#include <cstdint>

#define BATCH 8
#define SEQ   8192
#define BS    65536
#define MC    48
#define OF    88
#define NG    8
#define HD    6
#define KW    31
#define PADW  15
#define N144  144

// ---------------- device scratch ----------------
__device__ float g_qkv1[(size_t)BS * N144];
__device__ float g_x2  [(size_t)BS * 136];
__device__ float g_qkv2[(size_t)BS * N144];

// ============ bf16 split-precision mma.sync GEMM (round-14, passing) ======
__device__ __forceinline__ void mma_bf16(float& c0, float& c1, float& c2, float& c3,
                                         uint32_t a0, uint32_t a1, uint32_t a2, uint32_t a3,
                                         uint32_t b0, uint32_t b1) {
    asm volatile(
        "mma.sync.aligned.m16n8k16.row.col.f32.bf16.bf16.f32 "
        "{%0,%1,%2,%3}, {%4,%5,%6,%7}, {%8,%9}, {%0,%1,%2,%3};"
        : "+f"(c0), "+f"(c1), "+f"(c2), "+f"(c3)
        : "r"(a0), "r"(a1), "r"(a2), "r"(a3), "r"(b0), "r"(b1));
}

constexpr int KT   = 48;
constexpr int KTP  = 56;
constexpr int KTPW = 28;
constexpr int GSM_A = 128 * KTP;
constexpr int GSM_B = 144 * KTP;
constexpr int GEMM_SMEM = (2 * GSM_A + 2 * GSM_B) * 2;

template <int KSRC, int NCHUNK>
__global__ __launch_bounds__(256, 2) void gemm_qkv_mma(
    const float* __restrict__ x,
    const float* __restrict__ Wq, const float* __restrict__ Wk,
    const float* __restrict__ Wv,
    float* __restrict__ out)
{
    extern __shared__ __align__(16) char smem[];
    uint16_t* Ahi = reinterpret_cast<uint16_t*>(smem);
    uint16_t* Alo = Ahi + GSM_A;
    uint16_t* Bhi = Alo + GSM_A;
    uint16_t* Blo = Bhi + GSM_B;
    const uint32_t* Ahi32 = reinterpret_cast<const uint32_t*>(Ahi);
    const uint32_t* Alo32 = reinterpret_cast<const uint32_t*>(Alo);
    const uint32_t* Bhi32 = reinterpret_cast<const uint32_t*>(Bhi);
    const uint32_t* Blo32 = reinterpret_cast<const uint32_t*>(Blo);

    const int tid  = threadIdx.x;
    const int wid  = tid >> 5;
    const int lane = tid & 31;
    const int row0 = blockIdx.x * 128;

    float acc[18][4];
#pragma unroll
    for (int nt = 0; nt < 18; nt++)
#pragma unroll
        for (int j = 0; j < 4; j++) acc[nt][j] = 0.f;

    for (int c = 0; c < NCHUNK; c++) {
        const int kbase = c * KT;
        __syncthreads();
        for (int i = tid; i < 128 * KT; i += 256) {
            int m = i / KT, k = i - m * KT;
            int kg = kbase + k;
            float v = (kg < KSRC) ? x[(size_t)(row0 + m) * KSRC + kg] : 0.f;
            __nv_bfloat16 hi = __float2bfloat16_rn(v);
            __nv_bfloat16 lo = __float2bfloat16_rn(v - __bfloat162float(hi));
            Ahi[m * KTP + k] = *reinterpret_cast<uint16_t*>(&hi);
            Alo[m * KTP + k] = *reinterpret_cast<uint16_t*>(&lo);
        }
        for (int i = tid; i < 144 * KT; i += 256) {
            int n = i / KT, k = i - n * KT;
            int kg = kbase + k;
            float v = 0.f;
            if (kg < KSRC) {
                const float* Wp; int nr;
                if (n < 48)      { Wp = Wq; nr = n; }
                else if (n < 96) { Wp = Wk; nr = n - 48; }
                else             { Wp = Wv; nr = n - 96; }
                v = Wp[nr * KSRC + kg];
            }
            __nv_bfloat16 hi = __float2bfloat16_rn(v);
            __nv_bfloat16 lo = __float2bfloat16_rn(v - __bfloat162float(hi));
            Bhi[n * KTP + k] = *reinterpret_cast<uint16_t*>(&hi);
            Blo[n * KTP + k] = *reinterpret_cast<uint16_t*>(&lo);
        }
        __syncthreads();

        const int arow = wid * 16 + (lane >> 2);
        const int kq = lane & 3;
#pragma unroll
        for (int ks = 0; ks < KT / 16; ks++) {
            const int ab = arow * KTPW + ks * 8 + kq;
            uint32_t ah0 = Ahi32[ab];
            uint32_t ah1 = Ahi32[ab + 8 * KTPW];
            uint32_t ah2 = Ahi32[ab + 4];
            uint32_t ah3 = Ahi32[ab + 8 * KTPW + 4];
            uint32_t al0 = Alo32[ab];
            uint32_t al1 = Alo32[ab + 8 * KTPW];
            uint32_t al2 = Alo32[ab + 4];
            uint32_t al3 = Alo32[ab + 8 * KTPW + 4];
            const int bb = (lane >> 2) * KTPW + ks * 8 + kq;
#pragma unroll
            for (int nt = 0; nt < 18; nt++) {
                const int bi = bb + nt * 8 * KTPW;
                uint32_t bh0 = Bhi32[bi], bh1 = Bhi32[bi + 4];
                uint32_t bl0 = Blo32[bi], bl1 = Blo32[bi + 4];
                mma_bf16(acc[nt][0], acc[nt][1], acc[nt][2], acc[nt][3],
                         ah0, ah1, ah2, ah3, bh0, bh1);
                mma_bf16(acc[nt][0], acc[nt][1], acc[nt][2], acc[nt][3],
                         al0, al1, al2, al3, bh0, bh1);
                mma_bf16(acc[nt][0], acc[nt][1], acc[nt][2], acc[nt][3],
                         ah0, ah1, ah2, ah3, bl0, bl1);
            }
        }
    }

    const int r0 = row0 + wid * 16 + (lane >> 2);
    const int cb = (lane & 3) * 2;
#pragma unroll
    for (int nt = 0; nt < 18; nt++) {
        int n = nt * 8 + cb;
        *reinterpret_cast<float2*>(&out[(size_t)r0 * N144 + n]) =
            make_float2(acc[nt][0], acc[nt][1]);
        *reinterpret_cast<float2*>(&out[(size_t)(r0 + 8) * N144 + n]) =
            make_float2(acc[nt][2], acc[nt][3]);
    }
}

// ================= shared helpers for attention =================
__device__ __forceinline__ float dot8(const float* q, float4 a, float4 b) {
    float e = q[0] * a.x;
    e = fmaf(q[1], a.y, e); e = fmaf(q[2], a.z, e); e = fmaf(q[3], a.w, e);
    e = fmaf(q[4], b.x, e); e = fmaf(q[5], b.y, e); e = fmaf(q[6], b.z, e);
    e = fmaf(q[7], b.w, e);
    return e;
}

// ============ attn_first: 1 row/thread, RPB=32, all outputs staged ========
constexpr int RPB_F  = 32;
constexpr int HALO_F = RPB_F + 2 * PADW;           // 62
constexpr int KV8P   = 128;
constexpr int RELP8  = 64;
constexpr int XSP    = 52;

constexpr int F_KV  = 0;                            // [62][128] = 7936 (== 32*248 abuf)
constexpr int F_REL = F_KV + HALO_F * KV8P;         // 7936
constexpr int F_WOT = F_REL + KW * RELP8;           // 9920
constexpr int F_XS  = F_WOT + MC * OF;              // 14144 [32][52]
constexpr int F_BO  = F_XS + RPB_F * XSP;           // 15808
constexpr int F_LNG = F_BO + OF;
constexpr int F_LNB = F_LNG + MC;
constexpr int F_SMEM_F = F_LNB + MC;                // 15992
constexpr int F_SMEM_BYTES = F_SMEM_F * 4;          // 63968 -> 3 CTAs/SM

__global__ __launch_bounds__(256, 3) void attn_first(
    const float* __restrict__ rel,
    const float* __restrict__ lng, const float* __restrict__ lnb,
    const float* __restrict__ Wp,
    const float* __restrict__ bp,
    float* __restrict__ pred_out,
    float* __restrict__ a_out)
{
    extern __shared__ __align__(16) float sm[];
    float* kv8  = sm + F_KV;
    float* relT = sm + F_REL;
    float* WoT  = sm + F_WOT;
    float* xs   = sm + F_XS;
    float* boS  = sm + F_BO;
    float* lngS = sm + F_LNG;
    float* lnbS = sm + F_LNB;

    const float* qkv = g_qkv1;

    const int tid = threadIdx.x;
    const int row0 = blockIdx.x * RPB_F;
    const int bi = row0 / SEQ;
    const int lo = bi * SEQ, hi = lo + SEQ;

    // ---- stage k/v + rel + weights ----
    for (int i = tid; i < HALO_F * KV8P; i += 256) {
        int hr = i >> 7, col = i & 127;
        int quad = col >> 5;
        int w = col & 31;
        int g = w >> 2, dd = w & 3;
        int isB = quad & 1;
        int d = isB ? 4 + dd : dd;
        bool valid = (!isB) || (dd < 2);
        int rr = row0 - PADW + hr;
        float v = 0.f;
        if (valid && rr >= lo && rr < hi) {
            int srcbase = (quad < 2) ? 48 : 96;
            v = qkv[(size_t)rr * N144 + srcbase + g * HD + d];
        }
        kv8[i] = v;
    }
    for (int i = tid; i < KW * RELP8; i += 256) {
        int t = i >> 6, col = i & 63;
        int isB = col >> 5;
        int w = col & 31;
        int g = w >> 2, dd = w & 3;
        int d = isB ? 4 + dd : dd;
        bool valid = (!isB) || (dd < 2);
        relT[i] = valid ? rel[(g * HD + d) * KW + t] : 0.f;
    }
    for (int i = tid; i < OF * MC; i += 256) {
        int o = i / MC, c = i - o * MC;
        WoT[c * OF + o] = Wp[i];
    }
    if (tid < OF) boS[tid] = bp[tid];
    if (tid < MC) { lngS[tid] = lng[tid]; lnbS[tid] = lnb[tid]; }
    __syncthreads();

    // ---- per-(row, group) attention ----
    const int lrow = tid >> 3;
    const int g = tid & 7;
    const int row = row0 + lrow;
    const int gb = g * HD;

    float en[KW];
    {
        float qr[8];
        {
            const float2* qp = reinterpret_cast<const float2*>(qkv + (size_t)row * N144 + gb);
            float2 a = qp[0], b = qp[1], c = qp[2];
            qr[0]=a.x; qr[1]=a.y; qr[2]=b.x; qr[3]=b.y; qr[4]=c.x; qr[5]=c.y;
            qr[6]=0.f; qr[7]=0.f;
        }
#pragma unroll
        for (int t = 0; t < KW; t++) {
            float4 ra = *reinterpret_cast<const float4*>(relT + t * RELP8 + g * 4);
            float4 rb = *reinterpret_cast<const float4*>(relT + t * RELP8 + 32 + g * 4);
            const float* kr = kv8 + (lrow + t) * KV8P;
            float4 ka = *reinterpret_cast<const float4*>(kr + g * 4);
            float4 kb = *reinterpret_cast<const float4*>(kr + 32 + g * 4);
            en[t] = dot8(qr, ra, rb) + dot8(qr, ka, kb);
        }

        float mx = en[0];
#pragma unroll
        for (int t = 1; t < KW; t++) mx = fmaxf(mx, en[t]);
        float ss = 0.f;
#pragma unroll
        for (int t = 0; t < KW; t++) { en[t] = __expf(en[t] - mx); ss += en[t]; }
        float inv = 1.f / ss;
#pragma unroll
        for (int t = 0; t < KW; t++) en[t] *= inv;

        float xv[8] = {0,0,0,0,0,0,0,0};
#pragma unroll
        for (int t = 0; t < KW; t++) {
            const float* vr = kv8 + (lrow + t) * KV8P;
            float4 va = *reinterpret_cast<const float4*>(vr + 64 + g * 4);
            float4 vb = *reinterpret_cast<const float4*>(vr + 96 + g * 4);
            float w = en[t];
            xv[0] = fmaf(w, va.x, xv[0]); xv[1] = fmaf(w, va.y, xv[1]);
            xv[2] = fmaf(w, va.z, xv[2]); xv[3] = fmaf(w, va.w, xv[3]);
            xv[4] = fmaf(w, vb.x, xv[4]); xv[5] = fmaf(w, vb.y, xv[5]);
            xv[6] = fmaf(w, vb.z, xv[6]); xv[7] = fmaf(w, vb.w, xv[7]);
        }

        // layernorm across 8 group-lanes
        float a0 = 0.f, b0 = 0.f;
#pragma unroll
        for (int d = 0; d < 8; d++) { a0 += xv[d]; b0 = fmaf(xv[d], xv[d], b0); }
#pragma unroll
        for (int m = 1; m < 8; m <<= 1) {
            a0 += __shfl_xor_sync(0xffffffffu, a0, m);
            b0 += __shfl_xor_sync(0xffffffffu, b0, m);
        }
        float mu = a0 * (1.f / MC);
        float rstd = rsqrtf(b0 * (1.f / MC) - mu * mu + 1e-5f);
#pragma unroll
        for (int d = 0; d < HD; d++)
            xs[lrow * XSP + gb + d] = (xv[d] - mu) * rstd * lngS[gb + d] + lnbS[gb + d];
    }
    __syncthreads();     // kv reads + xs writes complete

    // ---- a_out: scatter to abuf (kv region, exact 32x248 fit), copy coalesced
    {
        float* abuf = sm + F_KV;
        float* d0 = abuf + lrow * 248 + g * KW;
#pragma unroll
        for (int t = 0; t < KW; t++) d0[t] = en[t];
    }
    __syncthreads();
    {
        float4* dst = reinterpret_cast<float4*>(a_out + (size_t)row0 * 248);
        const float4* src = reinterpret_cast<const float4*>(sm + F_KV);
        for (int i = tid; i < RPB_F * 248 / 4; i += 256) dst[i] = src[i];
    }
    __syncthreads();     // abuf free -> sigbuf

    // ---- projection + sigmoid into sigbuf [32][88] ----
    float* sigbuf = sm + F_KV;
    if (tid < 176) {
        const int rq = tid / 11;       // 0..15 -> rows rq*2, rq*2+1
        const int o8 = tid - rq * 11;
        float acc[2][8];
#pragma unroll
        for (int j = 0; j < 8; j++) {
            float b = boS[o8 * 8 + j];
            acc[0][j] = b; acc[1][j] = b;
        }
#pragma unroll
        for (int c = 0; c < MC; c++) {
            float4 w0 = *reinterpret_cast<const float4*>(&WoT[c * OF + o8 * 8]);
            float4 w1 = *reinterpret_cast<const float4*>(&WoT[c * OF + o8 * 8 + 4]);
            float wv[8] = {w0.x, w0.y, w0.z, w0.w, w1.x, w1.y, w1.z, w1.w};
            float a0 = xs[(rq * 2) * XSP + c];
            float a1 = xs[(rq * 2 + 1) * XSP + c];
#pragma unroll
            for (int j = 0; j < 8; j++) {
                acc[0][j] = fmaf(a0, wv[j], acc[0][j]);
                acc[1][j] = fmaf(a1, wv[j], acc[1][j]);
            }
        }
#pragma unroll
        for (int r = 0; r < 2; r++) {
            float* srow = sigbuf + (rq * 2 + r) * OF + o8 * 8;
#pragma unroll
            for (int j = 0; j < 8; j++)
                srow[j] = 1.f / (1.f + __expf(-acc[r][j]));
        }
    }
    __syncthreads();

    // ---- coalesced outputs: pred_out + g_x2 ----
    {
        float4* dst = reinterpret_cast<float4*>(pred_out + (size_t)row0 * OF);
        const float4* src = reinterpret_cast<const float4*>(sigbuf);
        for (int i = tid; i < RPB_F * OF / 4; i += 256) dst[i] = src[i];
    }
    {
        float4* dst = reinterpret_cast<float4*>(g_x2 + (size_t)row0 * 136);
        for (int i = tid; i < RPB_F * 34; i += 256) {
            int r = i / 34, c4 = i - r * 34;
            float4 v;
            if (c4 < 22)
                v = *reinterpret_cast<const float4*>(sigbuf + r * OF + c4 * 4);
            else
                v = *reinterpret_cast<const float4*>(xs + r * XSP + (c4 - 22) * 4);
            dst[i] = v;
        }
    }
}

// ============ attn_second: 2 rows/thread, RPB=64 (R15 false-path) =========
constexpr int RPB_S  = 64;
constexpr int HALO_S = RPB_S + 2 * PADW;            // 94

constexpr int S_KV  = 0;                             // [94][128] = 12032
constexpr int S_REL = S_KV + HALO_S * KV8P;          // 12032
constexpr int S_WOT = S_REL + KW * RELP8;            // 14016
constexpr int S_XS  = S_WOT + MC * OF;               // 18240 [64][52]
constexpr int S_BO  = S_XS + RPB_S * XSP;            // 21568
constexpr int S_LNG = S_BO + OF;
constexpr int S_LNB = S_LNG + MC;
constexpr int S_SMEM_F = S_LNB + MC;                 // 21752
constexpr int S_SMEM_BYTES = S_SMEM_F * 4;           // 87008 -> 2 CTAs/SM

__global__ __launch_bounds__(256, 2) void attn_second(
    const float* __restrict__ rel,
    const float* __restrict__ lng, const float* __restrict__ lnb,
    const float* __restrict__ Wp,
    const float* __restrict__ bp,
    float* __restrict__ pred_out)
{
    extern __shared__ __align__(16) float sm[];
    float* kv8  = sm + S_KV;
    float* relT = sm + S_REL;
    float* WoT  = sm + S_WOT;
    float* xs   = sm + S_XS;
    float* boS  = sm + S_BO;
    float* lngS = sm + S_LNG;
    float* lnbS = sm + S_LNB;

    const float* qkv = g_qkv2;

    const int tid = threadIdx.x;
    const int row0 = blockIdx.x * RPB_S;
    const int bi = row0 / SEQ;
    const int lo = bi * SEQ, hi = lo + SEQ;

    for (int i = tid; i < HALO_S * KV8P; i += 256) {
        int hr = i >> 7, col = i & 127;
        int quad = col >> 5;
        int w = col & 31;
        int g = w >> 2, dd = w & 3;
        int isB = quad & 1;
        int d = isB ? 4 + dd : dd;
        bool valid = (!isB) || (dd < 2);
        int rr = row0 - PADW + hr;
        float v = 0.f;
        if (valid && rr >= lo && rr < hi) {
            int srcbase = (quad < 2) ? 48 : 96;
            v = qkv[(size_t)rr * N144 + srcbase + g * HD + d];
        }
        kv8[i] = v;
    }
    for (int i = tid; i < KW * RELP8; i += 256) {
        int t = i >> 6, col = i & 63;
        int isB = col >> 5;
        int w = col & 31;
        int g = w >> 2, dd = w & 3;
        int d = isB ? 4 + dd : dd;
        bool valid = (!isB) || (dd < 2);
        relT[i] = valid ? rel[(g * HD + d) * KW + t] : 0.f;
    }
    for (int i = tid; i < OF * MC; i += 256) {
        int o = i / MC, c = i - o * MC;
        WoT[c * OF + o] = Wp[i];
    }
    if (tid < OF) boS[tid] = bp[tid];
    if (tid < MC) { lngS[tid] = lng[tid]; lnbS[tid] = lnb[tid]; }
    __syncthreads();

    {
        const int pair = tid >> 3;
        const int g = tid & 7;
        const int lr0 = pair * 2;
        const int row0g = row0 + lr0;
        const int gb = g * HD;

        float qr0[8], qr1[8];
        {
            const float2* q0 = reinterpret_cast<const float2*>(qkv + (size_t)row0g * N144 + gb);
            const float2* q1 = reinterpret_cast<const float2*>(qkv + (size_t)(row0g + 1) * N144 + gb);
            float2 a = q0[0], b = q0[1], c = q0[2];
            qr0[0]=a.x; qr0[1]=a.y; qr0[2]=b.x; qr0[3]=b.y; qr0[4]=c.x; qr0[5]=c.y;
            qr0[6]=0.f; qr0[7]=0.f;
            a = q1[0]; b = q1[1]; c = q1[2];
            qr1[0]=a.x; qr1[1]=a.y; qr1[2]=b.x; qr1[3]=b.y; qr1[4]=c.x; qr1[5]=c.y;
            qr1[6]=0.f; qr1[7]=0.f;
        }

        float en0[KW], en1[KW];
#pragma unroll
        for (int t = 0; t < KW; t++) {
            float4 ra = *reinterpret_cast<const float4*>(relT + t * RELP8 + g * 4);
            float4 rb = *reinterpret_cast<const float4*>(relT + t * RELP8 + 32 + g * 4);
            en0[t] = dot8(qr0, ra, rb);
            en1[t] = dot8(qr1, ra, rb);
        }
#pragma unroll
        for (int j = 0; j < 32; j++) {
            const float* kr = kv8 + (lr0 + j) * KV8P;
            float4 ka = *reinterpret_cast<const float4*>(kr + g * 4);
            float4 kb = *reinterpret_cast<const float4*>(kr + 32 + g * 4);
            if (j < 31) en0[j] += dot8(qr0, ka, kb);
            if (j > 0)  en1[j - 1] += dot8(qr1, ka, kb);
        }

        float mx0 = en0[0], mx1 = en1[0];
#pragma unroll
        for (int t = 1; t < KW; t++) { mx0 = fmaxf(mx0, en0[t]); mx1 = fmaxf(mx1, en1[t]); }
        float s0 = 0.f, s1 = 0.f;
#pragma unroll
        for (int t = 0; t < KW; t++) {
            en0[t] = __expf(en0[t] - mx0); s0 += en0[t];
            en1[t] = __expf(en1[t] - mx1); s1 += en1[t];
        }
        float i0 = 1.f / s0, i1 = 1.f / s1;
#pragma unroll
        for (int t = 0; t < KW; t++) { en0[t] *= i0; en1[t] *= i1; }

        float xv0[8] = {0,0,0,0,0,0,0,0}, xv1[8] = {0,0,0,0,0,0,0,0};
#pragma unroll
        for (int j = 0; j < 32; j++) {
            const float* vr = kv8 + (lr0 + j) * KV8P;
            float4 va = *reinterpret_cast<const float4*>(vr + 64 + g * 4);
            float4 vb = *reinterpret_cast<const float4*>(vr + 96 + g * 4);
            float fv[8] = {va.x, va.y, va.z, va.w, vb.x, vb.y, vb.z, vb.w};
            if (j < 31) {
                float w = en0[j];
#pragma unroll
                for (int d = 0; d < 8; d++) xv0[d] = fmaf(w, fv[d], xv0[d]);
            }
            if (j > 0) {
                float w = en1[j - 1];
#pragma unroll
                for (int d = 0; d < 8; d++) xv1[d] = fmaf(w, fv[d], xv1[d]);
            }
        }

        float a0 = 0.f, b0 = 0.f, a1 = 0.f, b1 = 0.f;
#pragma unroll
        for (int d = 0; d < 8; d++) {
            a0 += xv0[d]; b0 = fmaf(xv0[d], xv0[d], b0);
            a1 += xv1[d]; b1 = fmaf(xv1[d], xv1[d], b1);
        }
#pragma unroll
        for (int m = 1; m < 8; m <<= 1) {
            a0 += __shfl_xor_sync(0xffffffffu, a0, m);
            b0 += __shfl_xor_sync(0xffffffffu, b0, m);
            a1 += __shfl_xor_sync(0xffffffffu, a1, m);
            b1 += __shfl_xor_sync(0xffffffffu, b1, m);
        }
        float mu0 = a0 * (1.f / MC), mu1 = a1 * (1.f / MC);
        float r0 = rsqrtf(b0 * (1.f / MC) - mu0 * mu0 + 1e-5f);
        float r1 = rsqrtf(b1 * (1.f / MC) - mu1 * mu1 + 1e-5f);
#pragma unroll
        for (int d = 0; d < HD; d++) {
            xs[lr0 * XSP + gb + d] = (xv0[d] - mu0) * r0 * lngS[gb + d] + lnbS[gb + d];
            xs[(lr0 + 1) * XSP + gb + d] = (xv1[d] - mu1) * r1 * lngS[gb + d] + lnbS[gb + d];
        }
    }
    __syncthreads();

    float* sigbuf = sm + S_KV;
    if (tid < 176) {
        const int rq = tid / 11;
        const int o8 = tid - rq * 11;
        float acc[4][8];
#pragma unroll
        for (int j = 0; j < 8; j++) {
            float b = boS[o8 * 8 + j];
#pragma unroll
            for (int r = 0; r < 4; r++) acc[r][j] = b;
        }
#pragma unroll
        for (int c = 0; c < MC; c++) {
            float4 w0 = *reinterpret_cast<const float4*>(&WoT[c * OF + o8 * 8]);
            float4 w1 = *reinterpret_cast<const float4*>(&WoT[c * OF + o8 * 8 + 4]);
            float wv[8] = {w0.x, w0.y, w0.z, w0.w, w1.x, w1.y, w1.z, w1.w};
#pragma unroll
            for (int r = 0; r < 4; r++) {
                float a = xs[(rq * 4 + r) * XSP + c];
#pragma unroll
                for (int j = 0; j < 8; j++)
                    acc[r][j] = fmaf(a, wv[j], acc[r][j]);
            }
        }
#pragma unroll
        for (int r = 0; r < 4; r++) {
            float* srow = sigbuf + (rq * 4 + r) * OF + o8 * 8;
#pragma unroll
            for (int j = 0; j < 8; j++)
                srow[j] = 1.f / (1.f + __expf(-acc[r][j]));
        }
    }
    __syncthreads();

    {
        float4* dst = reinterpret_cast<float4*>(pred_out + (size_t)row0 * OF);
        const float4* src = reinterpret_cast<const float4*>(sigbuf);
        for (int i = tid; i < RPB_S * OF / 4; i += 256) dst[i] = src[i];
    }
}

// ---------------- launch ----------------
extern "C" void kernel_launch(void* const* d_in, const int* in_sizes, int n_in,
                              void* d_out, int out_size)
{
    const float* spec = (const float*)d_in[0];
    const float* Wq1  = (const float*)d_in[1];
    const float* Wk1  = (const float*)d_in[2];
    const float* Wv1  = (const float*)d_in[3];
    const float* rel1 = (const float*)d_in[4];
    const float* ln1g = (const float*)d_in[5];
    const float* ln1b = (const float*)d_in[6];
    const float* Wo   = (const float*)d_in[7];
    const float* bo   = (const float*)d_in[8];
    const float* Wq2  = (const float*)d_in[9];
    const float* Wk2  = (const float*)d_in[10];
    const float* Wv2  = (const float*)d_in[11];
    const float* rel2 = (const float*)d_in[12];
    const float* ln2g = (const float*)d_in[13];
    const float* ln2b = (const float*)d_in[14];
    const float* Wf   = (const float*)d_in[15];
    const float* bf   = (const float*)d_in[16];

    float* out = (float*)d_out;
    float* frame = out;
    float* onset = out + (size_t)BS * OF;
    float* aout  = out + (size_t)2 * BS * OF;

    void* p_x2;   cudaGetSymbolAddress(&p_x2, g_x2);
    void* p_qkv1; cudaGetSymbolAddress(&p_qkv1, g_qkv1);
    void* p_qkv2; cudaGetSymbolAddress(&p_qkv2, g_qkv2);

    cudaFuncSetAttribute(gemm_qkv_mma<229, 5>,
        cudaFuncAttributeMaxDynamicSharedMemorySize, GEMM_SMEM);
    cudaFuncSetAttribute(gemm_qkv_mma<136, 3>,
        cudaFuncAttributeMaxDynamicSharedMemorySize, GEMM_SMEM);
    cudaFuncSetAttribute(attn_first,
        cudaFuncAttributeMaxDynamicSharedMemorySize, F_SMEM_BYTES);
    cudaFuncSetAttribute(attn_second,
        cudaFuncAttributeMaxDynamicSharedMemorySize, S_SMEM_BYTES);

    gemm_qkv_mma<229, 5><<<BS / 128, 256, GEMM_SMEM>>>(spec, Wq1, Wk1, Wv1,
                                                       (float*)p_qkv1);
    attn_first<<<BS / RPB_F, 256, F_SMEM_BYTES>>>(
        rel1, ln1g, ln1b, Wo, bo, onset, aout);
    gemm_qkv_mma<136, 3><<<BS / 128, 256, GEMM_SMEM>>>((const float*)p_x2,
                                                       Wq2, Wk2, Wv2,
                                                       (float*)p_qkv2);
    attn_second<<<BS / RPB_S, 256, S_SMEM_BYTES>>>(
        rel2, ln2g, ln2b, Wf, bf, frame);
}